// round 7
// baseline (speedup 1.0000x reference)
#include <cuda_runtime.h>
#include <math.h>

// ---------------------------------------------------------------------------
// DiffusionLoss fused single-kernel, occupancy-focused round:
//   TILE=128, 256 threads/block, __launch_bounds__(256,4) -> 4 blocks/SM,
//   32 warps/SM. grid = B * ntri(136) = 544 blocks.
//   thread t: rows 2*(t&63)+{0,1}, j-quarter (t>>6) (32 j's) of a 128x128 tile.
//   Inner loop: packed f32x2 (dp2,dg2) = 3 FMA2 + 1 ADD2, one MUFU sqrt/pair.
//   Diagonal blocks (first B*tilesI ids, all wave-1): stats partials -> last
//   per batch solves 3x3 Kabsch -> flag -> fused alignment loss.
//   Globally last block combines + writes out + resets (graph-replay safe).
// ---------------------------------------------------------------------------

#define MAXB 16
#define MAXBLK 64
#define TILE 128
#define NTHR 256

__device__ double   g_part[MAXB][MAXBLK][16];
__device__ unsigned g_cnt[MAXB];
__device__ int      g_ready[MAXB];
__device__ float    g_par[MAXB][15];  // R[9], mu[3], muGT[3]
__device__ double   g_W[MAXB];
__device__ double   g_num1[MAXB];
__device__ double   g_bond;
__device__ unsigned g_done;

__device__ __forceinline__ float fsqrt_approx(float x) {
    float r;
    asm("sqrt.approx.f32 %0, %1;" : "=f"(r) : "f"(x));
    return r;
}

#define PACK_F32X2(out, lo, hi) \
    asm("mov.b64 %0, {%1, %2};" : "=l"(out) : "f"(lo), "f"(hi))
#define UNPACK_F32X2(lo, hi, in) \
    asm("mov.b64 {%0, %1}, %2;" : "=f"(lo), "=f"(hi) : "l"(in))
#define ADD_F32X2(out, a, b) \
    asm("add.rn.f32x2 %0, %1, %2;" : "=l"(out) : "l"(a), "l"(b))
#define FMA_F32X2(d, a, b, c) \
    asm("fma.rn.f32x2 %0, %1, %2, %3;" : "=l"(d) : "l"(a), "l"(b), "l"(c))

// ---------------------------------------------------------------------------
// 3x3 Kabsch solve from accumulated moments v[16] (thread-serial, float).
// ---------------------------------------------------------------------------
__device__ void kabsch_solve(const double* v, int b)
{
    double W = v[0];
    double invW = 1.0 / W;
    // mu = GT weighted mean, muGT = pred mean (arg-swap in reference)
    float muGT[3] = { (float)(v[1]*invW), (float)(v[2]*invW), (float)(v[3]*invW) };
    float mu[3]   = { (float)(v[4]*invW), (float)(v[5]*invW), (float)(v[6]*invW) };

    float A[3][3];
    for (int i = 0; i < 3; i++)
        for (int j = 0; j < 3; j++)
            A[i][j] = (float)(v[7 + i*3 + j] - v[1+i]*v[4+j]*invW);

    float detA = A[0][0]*(A[1][1]*A[2][2]-A[1][2]*A[2][1])
               - A[0][1]*(A[1][0]*A[2][2]-A[1][2]*A[2][0])
               + A[0][2]*(A[1][0]*A[2][1]-A[1][1]*A[2][0]);

    float C[3][3];
    for (int i = 0; i < 3; i++)
        for (int j = 0; j < 3; j++) {
            float s = 0.f;
            for (int k = 0; k < 3; k++) s += A[k][i]*A[k][j];
            C[i][j] = s;
        }
    float V[3][3] = {{1,0,0},{0,1,0},{0,0,1}};
#pragma unroll
    for (int sweep = 0; sweep < 6; sweep++) {
#pragma unroll
        for (int p = 0; p < 3; p++)
#pragma unroll
            for (int q = p+1; q < 3; q++) {
                float apq = C[p][q];
                if (apq == 0.f) continue;
                float theta = __fdividef(C[q][q] - C[p][p], 2.f * apq);
                float tt = (theta >= 0.f ? 1.f : -1.f) *
                           __fdividef(1.f, fabsf(theta) + sqrtf(theta*theta + 1.f));
                float c = rsqrtf(tt*tt + 1.f), s = tt * c;
                for (int k = 0; k < 3; k++) {
                    float a = C[k][p], bb = C[k][q];
                    C[k][p] = c*a - s*bb;  C[k][q] = s*a + c*bb;
                }
                for (int k = 0; k < 3; k++) {
                    float a = C[p][k], bb = C[q][k];
                    C[p][k] = c*a - s*bb;  C[q][k] = s*a + c*bb;
                }
                for (int k = 0; k < 3; k++) {
                    float a = V[k][p], bb = V[k][q];
                    V[k][p] = c*a - s*bb;  V[k][q] = s*a + c*bb;
                }
            }
    }
    float eig[3] = { C[0][0], C[1][1], C[2][2] };
    int idx[3] = {0, 1, 2};
    for (int i = 0; i < 2; i++)
        for (int j = i+1; j < 3; j++)
            if (eig[idx[j]] > eig[idx[i]]) { int tmp = idx[i]; idx[i] = idx[j]; idx[j] = tmp; }

    float emax = fmaxf(eig[idx[0]], 0.f);
    float dinv[3];
    for (int i = 0; i < 3; i++) {
        float e = fmaxf(eig[idx[i]], 0.f);
        dinv[i] = (e > 1e-12f * emax && e > 0.f) ? rsqrtf(e) : 0.f;
    }
    if (detA < 0.f) dinv[2] = -dinv[2];

    float T[3][3];
    for (int i = 0; i < 3; i++)
        for (int j = 0; j < 3; j++) {
            float s = 0.f;
            for (int k = 0; k < 3; k++) s += A[i][k] * V[k][idx[j]];
            T[i][j] = s * dinv[j];
        }
    for (int i = 0; i < 3; i++)
        for (int j = 0; j < 3; j++) {
            float s = 0.f;
            for (int k = 0; k < 3; k++) s += T[i][k] * V[j][idx[k]];
            g_par[b][i*3 + j] = s;
        }
    g_par[b][9]  = mu[0];   g_par[b][10] = mu[1];   g_par[b][11] = mu[2];
    g_par[b][12] = muGT[0]; g_par[b][13] = muGT[1]; g_par[b][14] = muGT[2];
    g_W[b] = W;
}

// ---------------------------------------------------------------------------
// Fallback K1 (used when diagonal blocks wouldn't fit in wave 1).
// ---------------------------------------------------------------------------
__global__ void __launch_bounds__(256)
reduce_solve_kernel(const float* __restrict__ pred,
                    const float* __restrict__ gt,
                    const float* __restrict__ w,
                    int N, int blocksPerB)
{
    const int b   = blockIdx.x / blocksPerB;
    const int blk = blockIdx.x % blocksPerB;
    const int t   = threadIdx.x;
    const float* pb = pred + (size_t)b * N * 3;
    const float* gb = gt   + (size_t)b * N * 3;
    const float* wb = w    + (size_t)b * N;

    float acc[16];
#pragma unroll
    for (int i = 0; i < 16; i++) acc[i] = 0.f;
    for (int n = blk * blockDim.x + t; n < N; n += blocksPerB * blockDim.x) {
        float wn = wb[n];
        float px = pb[3*n], py = pb[3*n+1], pz = pb[3*n+2];
        float gx = gb[3*n], gy = gb[3*n+1], gz = gb[3*n+2];
        float wpx = wn*px, wpy = wn*py, wpz = wn*pz;
        acc[0] += wn;
        acc[1] += wpx;  acc[2] += wpy;  acc[3] += wpz;
        acc[4] += wn*gx; acc[5] += wn*gy; acc[6] += wn*gz;
        acc[7] += wpx*gx; acc[8] += wpx*gy; acc[9] += wpx*gz;
        acc[10] += wpy*gx; acc[11] += wpy*gy; acc[12] += wpy*gz;
        acc[13] += wpz*gx; acc[14] += wpz*gy; acc[15] += wpz*gz;
    }
    const unsigned mask = 0xffffffffu;
#pragma unroll
    for (int i = 0; i < 16; i++)
        for (int o = 16; o > 0; o >>= 1)
            acc[i] += __shfl_down_sync(mask, acc[i], o);
    __shared__ double sred[8][16];
    int warp = t >> 5, lane = t & 31;
    if (lane == 0)
#pragma unroll
        for (int i = 0; i < 16; i++) sred[warp][i] = (double)acc[i];
    __syncthreads();
    if (t != 0) return;
    double v[16];
#pragma unroll
    for (int i = 0; i < 16; i++) {
        double s = 0.0;
        for (int wi = 0; wi < 8; wi++) s += sred[wi][i];
        g_part[b][blk][i] = s;
    }
    __threadfence();
    unsigned old = atomicInc(&g_cnt[b], (unsigned)(blocksPerB - 1));
    if (old != (unsigned)(blocksPerB - 1)) return;
    __threadfence();
    double vv[16];
    for (int i = 0; i < 16; i++) {
        double s = 0.0;
        for (int k = 0; k < blocksPerB; k++) s += g_part[b][k][i];
        vv[i] = s;
    }
    kabsch_solve(vv, b);
    g_num1[b] = 0.0;
    if (b == 0) g_bond = 0.0;
    __threadfence();
}

// ---------------------------------------------------------------------------
// Fused kernel: 128x128 tiles, thread t -> rows 2*(t&63)+{0,1}, jq = t>>6.
// ---------------------------------------------------------------------------
__global__ void __launch_bounds__(NTHR, 4)
fused_kernel(const float* __restrict__ pred,
             const float* __restrict__ gt,
             const float* __restrict__ w,
             const float* __restrict__ ht,
             float* __restrict__ out,
             int N, int B, int tilesI, int ntri, int precomputed)
{
    const int t  = threadIdx.x;
    const int rp = t & 63;           // row-pair index (64 pairs = 128 rows)
    const int jq = t >> 6;           // j quarter 0..3 (32 j's each)
    const int nOff = ntri - tilesI;
    const int blk = blockIdx.x;

    int b, ti, tj;
    bool diag;
    if (blk < B * tilesI) {          // diagonal tiles first: wave 1
        diag = true;
        b = blk / tilesI;
        ti = tj = blk % tilesI;
    } else {
        diag = false;
        int rem = blk - B * tilesI;
        b = rem / nOff;
        int r2 = rem % nOff;
        ti = 0;
        int rowlen = tilesI - 1;
        while (r2 >= rowlen) { r2 -= rowlen; ti++; rowlen--; }
        tj = ti + 1 + r2;
    }

    const float* pb = pred + (size_t)b * N * 3;
    const float* gb = gt   + (size_t)b * N * 3;
    const float* wb = w    + (size_t)b * N;

    __shared__ float4 sA[TILE];   // (pjx, gjx, pjy, gjy)
    __shared__ float4 sZ[TILE];   // (pjz, gjz, pn2j, gn2j)
    __shared__ float  sW[TILE];
    __shared__ double sred[2][16];
    __shared__ double sredp[NTHR/32];
    __shared__ double sreda[2];

    // ---- load j tile (threads 0..127) ----
    if (t < TILE) {
        int j = tj * TILE + t;
        float px=0.f,py=0.f,pz=0.f,gx=0.f,gy=0.f,gz=0.f,wj=0.f;
        if (j < N) {
            px = pb[3*j]; py = pb[3*j+1]; pz = pb[3*j+2];
            gx = gb[3*j]; gy = gb[3*j+1]; gz = gb[3*j+2];
            wj = wb[j];
        }
        sA[t] = make_float4(px, gx, py, gy);
        sZ[t] = make_float4(pz, gz, px*px+py*py+pz*pz, gx*gx+gy*gy+gz*gz);
        sW[t] = wj;
    }

    // ---- load the two i-rows into registers ----
    int i0 = ti * TILE + 2*rp;
    int i1 = i0 + 1;
    float p0x=0.f,p0y=0.f,p0z=0.f,g0x=0.f,g0y=0.f,g0z=0.f,w0=0.f;
    float p1x=0.f,p1y=0.f,p1z=0.f,g1x=0.f,g1y=0.f,g1z=0.f,w1=0.f;
    if (i0 < N) {
        p0x = pb[3*i0]; p0y = pb[3*i0+1]; p0z = pb[3*i0+2]; w0 = wb[i0];
        g0x = gb[3*i0]; g0y = gb[3*i0+1]; g0z = gb[3*i0+2];
    }
    if (i1 < N) {
        p1x = pb[3*i1]; p1y = pb[3*i1+1]; p1z = pb[3*i1+2]; w1 = wb[i1];
        g1x = gb[3*i1]; g1y = gb[3*i1+1]; g1z = gb[3*i1+2];
    }

    unsigned long long ax0, ay0, az0, bs0, ax1, ay1, az1, bs1;
    PACK_F32X2(ax0, -2.f*p0x, -2.f*g0x);
    PACK_F32X2(ay0, -2.f*p0y, -2.f*g0y);
    PACK_F32X2(az0, -2.f*p0z, -2.f*g0z);
    PACK_F32X2(bs0, p0x*p0x+p0y*p0y+p0z*p0z, g0x*g0x+g0y*g0y+g0z*g0z);
    PACK_F32X2(ax1, -2.f*p1x, -2.f*g1x);
    PACK_F32X2(ay1, -2.f*p1y, -2.f*g1y);
    PACK_F32X2(az1, -2.f*p1z, -2.f*g1z);
    PACK_F32X2(bs1, p1x*p1x+p1y*p1y+p1z*p1z, g1x*g1x+g1y*g1y+g1z*g1z);

    const unsigned mask = 0xffffffffu;
    int warp = t >> 5, lane = t & 31;

    // ---- stats partial (diagonal blocks; threads t<64 own the 128 rows) ----
    if (diag && !precomputed && t < 64) {
        float acc[16];
        {
            float wpx0 = w0*p0x, wpy0 = w0*p0y, wpz0 = w0*p0z;
            float wpx1 = w1*p1x, wpy1 = w1*p1y, wpz1 = w1*p1z;
            acc[0] = w0 + w1;
            acc[1] = wpx0 + wpx1;  acc[2] = wpy0 + wpy1;  acc[3] = wpz0 + wpz1;
            acc[4] = w0*g0x + w1*g1x; acc[5] = w0*g0y + w1*g1y; acc[6] = w0*g0z + w1*g1z;
            acc[7]  = wpx0*g0x + wpx1*g1x; acc[8]  = wpx0*g0y + wpx1*g1y; acc[9]  = wpx0*g0z + wpx1*g1z;
            acc[10] = wpy0*g0x + wpy1*g1x; acc[11] = wpy0*g0y + wpy1*g1y; acc[12] = wpy0*g0z + wpy1*g1z;
            acc[13] = wpz0*g0x + wpz1*g1x; acc[14] = wpz0*g0y + wpz1*g1y; acc[15] = wpz0*g0z + wpz1*g1z;
        }
#pragma unroll
        for (int i = 0; i < 16; i++)
            for (int o = 16; o > 0; o >>= 1)
                acc[i] += __shfl_down_sync(mask, acc[i], o);
        if (lane == 0)
#pragma unroll
            for (int i = 0; i < 16; i++) sred[warp][i] = (double)acc[i];
    }
    __syncthreads();   // tile fill + sred writes visible

    if (diag && !precomputed && t == 0) {
        double v[16];
#pragma unroll
        for (int i = 0; i < 16; i++)
            g_part[b][ti][i] = sred[0][i] + sred[1][i];
        __threadfence();
        unsigned old = atomicInc(&g_cnt[b], (unsigned)(tilesI - 1));
        if (old == (unsigned)(tilesI - 1)) {
            __threadfence();
            double vv[16];
            for (int i = 0; i < 16; i++) {
                double s = 0.0;
                for (int k = 0; k < tilesI; k++) s += g_part[b][k][i];
                vv[i] = s;
            }
            kabsch_solve(vv, b);
            __threadfence();
            atomicExch(&g_ready[b], 1);
        }
    }

    // ---- bond quarter-tile: 2 rows x 32 j ----
    float acc0 = 0.f, acc1 = 0.f;
    const int kbase = jq * 32;
#pragma unroll 8
    for (int kk = 0; kk < 32; kk++) {
        int k = kbase + kk;
        ulonglong2 A = *reinterpret_cast<const ulonglong2*>(&sA[k]);
        ulonglong2 Z = *reinterpret_cast<const ulonglong2*>(&sZ[k]);
        float wj = sW[k];
        // row 0
        {
            unsigned long long c;
            FMA_F32X2(c, az0, Z.x, Z.y);   // -2z*zj + (pn2j,gn2j)
            FMA_F32X2(c, ay0, A.y, c);
            FMA_F32X2(c, ax0, A.x, c);
            ADD_F32X2(c, c, bs0);          // + (pn2i,gn2i) -> (dp2,dg2)
            float dp2, dg2;
            UNPACK_F32X2(dp2, dg2, c);
            float prod = fmaxf(dp2 * dg2, 0.f);
            float s = fsqrt_approx(prod);
            acc0 = fmaf(wj, fmaf(-2.f, s, dp2 + dg2), acc0);
        }
        // row 1
        {
            unsigned long long c;
            FMA_F32X2(c, az1, Z.x, Z.y);
            FMA_F32X2(c, ay1, A.y, c);
            FMA_F32X2(c, ax1, A.x, c);
            ADD_F32X2(c, c, bs1);
            float dp2, dg2;
            UNPACK_F32X2(dp2, dg2, c);
            float prod = fmaxf(dp2 * dg2, 0.f);
            float s = fsqrt_approx(prod);
            acc1 = fmaf(wj, fmaf(-2.f, s, dp2 + dg2), acc1);
        }
    }

    double tot = (double)(acc0 * w0) + (double)(acc1 * w1);
    if (!diag) tot *= 2.0;         // symmetry
    for (int o = 16; o > 0; o >>= 1)
        tot += __shfl_down_sync(mask, tot, o);
    if (lane == 0) sredp[warp] = tot;

    // ---- fused alignment loss (diagonal blocks; threads t<64) ----
    if (diag) {
        if (!precomputed && t == 0) {
            while (atomicAdd(&g_ready[b], 0) == 0) {}
            __threadfence();
        }
        __syncthreads();
        if (t < 64) {
            float R00 = g_par[b][0], R01 = g_par[b][1], R02 = g_par[b][2];
            float R10 = g_par[b][3], R11 = g_par[b][4], R12 = g_par[b][5];
            float R20 = g_par[b][6], R21 = g_par[b][7], R22 = g_par[b][8];
            float mux = g_par[b][9],  muy = g_par[b][10], muz = g_par[b][11];
            float mgx = g_par[b][12], mgy = g_par[b][13], mgz = g_par[b][14];

            float alf = 0.f;
            {
                float gx = g0x - mux, gy = g0y - muy, gz = g0z - muz;
                float ax = R00*gx + R01*gy + R02*gz + mgx;
                float ay = R10*gx + R11*gy + R12*gz + mgy;
                float az = R20*gx + R21*gy + R22*gz + mgz;
                float dx = p0x - ax, dy = p0y - ay, dz = p0z - az;
                alf += w0 * fsqrt_approx(dx*dx + dy*dy + dz*dz);
            }
            {
                float gx = g1x - mux, gy = g1y - muy, gz = g1z - muz;
                float ax = R00*gx + R01*gy + R02*gz + mgx;
                float ay = R10*gx + R11*gy + R12*gz + mgy;
                float az = R20*gx + R21*gy + R22*gz + mgz;
                float dx = p1x - ax, dy = p1y - ay, dz = p1z - az;
                alf += w1 * fsqrt_approx(dx*dx + dy*dy + dz*dz);
            }
            double al = (double)alf;
            for (int o = 16; o > 0; o >>= 1)
                al += __shfl_down_sync(mask, al, o);
            if (lane == 0) sreda[warp] = al;
        }
        __syncthreads();
        if (t == 0)
            atomicAdd(&g_num1[b], sreda[0] + sreda[1]);
    }
    __syncthreads();

    // ---- block totals + global completion ----
    if (t == 0) {
        double s = 0.0;
        for (int wi = 0; wi < NTHR/32; wi++) s += sredp[wi];
        atomicAdd(&g_bond, s);
        __threadfence();
        unsigned old = atomicInc(&g_done, (unsigned)(gridDim.x - 1));
        if (old == (unsigned)(gridDim.x - 1)) {
            __threadfence();
            double sw = 0.0, sw2 = 0.0, sn = 0.0;
            for (int bb = 0; bb < B; bb++) {
                double W = g_W[bb];
                sw += W; sw2 += W * W; sn += g_num1[bb];
            }
            double loss = sn / sw + g_bond / sw2;   // ALPHA_BOND = 1
            for (int bb = 0; bb < B; bb++) {
                double h = (double)ht[bb];
                out[bb] = (float)(((h*h + 256.0) / ((h + 16.0) * (h + 16.0))) * loss);
            }
            g_bond = 0.0;
            for (int bb = 0; bb < B; bb++) { g_num1[bb] = 0.0; g_ready[bb] = 0; }
            __threadfence();
        }
    }
}

extern "C" void kernel_launch(void* const* d_in, const int* in_sizes, int n_in,
                              void* d_out, int out_size)
{
    const float* pred = (const float*)d_in[0];
    const float* gt   = (const float*)d_in[1];
    const float* ht   = (const float*)d_in[2];
    const float* w    = (const float*)d_in[3];
    int B = in_sizes[2];
    int N = in_sizes[3] / B;

    int tilesI = (N + TILE - 1) / TILE;
    int ntri = tilesI * (tilesI + 1) / 2;
    int grid = B * ntri;

    // Spin-safety needs all diagonal blocks (ids < B*tilesI) in wave 1.
    if (B * tilesI <= 148 && tilesI <= MAXBLK && B <= MAXB) {
        fused_kernel<<<grid, NTHR>>>(pred, gt, w, ht, (float*)d_out,
                                     N, B, tilesI, ntri, 0);
    } else {
        int blocksPerB = (N + 255) / 256;
        if (blocksPerB > MAXBLK) blocksPerB = MAXBLK;
        reduce_solve_kernel<<<B * blocksPerB, 256>>>(pred, gt, w, N, blocksPerB);
        fused_kernel<<<grid, NTHR>>>(pred, gt, w, ht, (float*)d_out,
                                     N, B, tilesI, ntri, 1);
    }
}

// round 8
// speedup vs baseline: 1.2049x; 1.2049x over previous
#include <cuda_runtime.h>
#include <math.h>

// ---------------------------------------------------------------------------
// DiffusionLoss fused single-kernel.
// grid = B * ntri (36) = 144 blocks x 512 threads, all co-resident.
// Bond term decomposition:
//   sum_ij wi wj (dp-dg)^2 = [closed form O(N)] - 2 * sum_ij wi wj dp*dg
// so the O(N^2) loop computes only wi wj sqrt(dp2*dg2):
//   per pair: 3 FMA2 + 1 ADD2 (packed f32x2 dp2,dg2) + FMUL + FMNMX + MUFU
//             + FFMA  (~9 issues incl LDS share, 4-row blocking).
// Diagonal blocks: 18-moment stats partials -> last per batch does the 3x3
// Kabsch solve + closed form -> release flag -> fused alignment loss.
// Globally last block: final combine + out + state reset (replay-safe).
// ---------------------------------------------------------------------------

#define MAXB 16
#define MAXBLK 64
#define TILE 256
#define NTHR 512
#define NMOM 18

__device__ double   g_part[MAXB][MAXBLK][NMOM];
__device__ unsigned g_cnt[MAXB];
__device__ int      g_ready[MAXB];
__device__ float    g_par[MAXB][15];   // R[9], mu[3], muGT[3]
__device__ double   g_W[MAXB];
__device__ double   g_closed[MAXB];    // closed-form sum_ij wiwj (dp2+dg2)
__device__ double   g_num1[MAXB];
__device__ double   g_bond;            // sum_ij wi wj dp*dg (full matrix)
__device__ unsigned g_done;

__device__ __forceinline__ float fsqrt_approx(float x) {
    float r;
    asm("sqrt.approx.f32 %0, %1;" : "=f"(r) : "f"(x));
    return r;
}

#define PACK_F32X2(out, lo, hi) \
    asm("mov.b64 %0, {%1, %2};" : "=l"(out) : "f"(lo), "f"(hi))
#define UNPACK_F32X2(lo, hi, in) \
    asm("mov.b64 {%0, %1}, %2;" : "=f"(lo), "=f"(hi) : "l"(in))
#define ADD_F32X2(out, a, b) \
    asm("add.rn.f32x2 %0, %1, %2;" : "=l"(out) : "l"(a), "l"(b))
#define FMA_F32X2(d, a, b, c) \
    asm("fma.rn.f32x2 %0, %1, %2, %3;" : "=l"(d) : "l"(a), "l"(b), "l"(c))

// ---------------------------------------------------------------------------
// 3x3 Kabsch solve from moments v[18]; also stores the closed-form term.
// ---------------------------------------------------------------------------
__device__ void kabsch_solve(const double* v, int b)
{
    double W = v[0];
    double invW = 1.0 / W;
    // closed form: sum_ij wiwj dp2 = 2(W*Sp2w - |Spw|^2); same for g.
    double spw2 = v[1]*v[1] + v[2]*v[2] + v[3]*v[3];
    double sgw2 = v[4]*v[4] + v[5]*v[5] + v[6]*v[6];
    g_closed[b] = 2.0*(W*v[16] - spw2) + 2.0*(W*v[17] - sgw2);

    // mu = GT weighted mean, muGT = pred mean (arg-swap in reference)
    float muGT[3] = { (float)(v[1]*invW), (float)(v[2]*invW), (float)(v[3]*invW) };
    float mu[3]   = { (float)(v[4]*invW), (float)(v[5]*invW), (float)(v[6]*invW) };

    float A[3][3];
    for (int i = 0; i < 3; i++)
        for (int j = 0; j < 3; j++)
            A[i][j] = (float)(v[7 + i*3 + j] - v[1+i]*v[4+j]*invW);

    float detA = A[0][0]*(A[1][1]*A[2][2]-A[1][2]*A[2][1])
               - A[0][1]*(A[1][0]*A[2][2]-A[1][2]*A[2][0])
               + A[0][2]*(A[1][0]*A[2][1]-A[1][1]*A[2][0]);

    float C[3][3];
    for (int i = 0; i < 3; i++)
        for (int j = 0; j < 3; j++) {
            float s = 0.f;
            for (int k = 0; k < 3; k++) s += A[k][i]*A[k][j];
            C[i][j] = s;
        }
    float V[3][3] = {{1,0,0},{0,1,0},{0,0,1}};
#pragma unroll
    for (int sweep = 0; sweep < 6; sweep++) {
#pragma unroll
        for (int p = 0; p < 3; p++)
#pragma unroll
            for (int q = p+1; q < 3; q++) {
                float apq = C[p][q];
                if (apq == 0.f) continue;
                float theta = __fdividef(C[q][q] - C[p][p], 2.f * apq);
                float tt = (theta >= 0.f ? 1.f : -1.f) *
                           __fdividef(1.f, fabsf(theta) + sqrtf(theta*theta + 1.f));
                float c = rsqrtf(tt*tt + 1.f), s = tt * c;
                for (int k = 0; k < 3; k++) {
                    float a = C[k][p], bb = C[k][q];
                    C[k][p] = c*a - s*bb;  C[k][q] = s*a + c*bb;
                }
                for (int k = 0; k < 3; k++) {
                    float a = C[p][k], bb = C[q][k];
                    C[p][k] = c*a - s*bb;  C[q][k] = s*a + c*bb;
                }
                for (int k = 0; k < 3; k++) {
                    float a = V[k][p], bb = V[k][q];
                    V[k][p] = c*a - s*bb;  V[k][q] = s*a + c*bb;
                }
            }
    }
    float eig[3] = { C[0][0], C[1][1], C[2][2] };
    int idx[3] = {0, 1, 2};
    for (int i = 0; i < 2; i++)
        for (int j = i+1; j < 3; j++)
            if (eig[idx[j]] > eig[idx[i]]) { int tmp = idx[i]; idx[i] = idx[j]; idx[j] = tmp; }

    float emax = fmaxf(eig[idx[0]], 0.f);
    float dinv[3];
    for (int i = 0; i < 3; i++) {
        float e = fmaxf(eig[idx[i]], 0.f);
        dinv[i] = (e > 1e-12f * emax && e > 0.f) ? rsqrtf(e) : 0.f;
    }
    if (detA < 0.f) dinv[2] = -dinv[2];

    float T[3][3];
    for (int i = 0; i < 3; i++)
        for (int j = 0; j < 3; j++) {
            float s = 0.f;
            for (int k = 0; k < 3; k++) s += A[i][k] * V[k][idx[j]];
            T[i][j] = s * dinv[j];
        }
    for (int i = 0; i < 3; i++)
        for (int j = 0; j < 3; j++) {
            float s = 0.f;
            for (int k = 0; k < 3; k++) s += T[i][k] * V[j][idx[k]];
            g_par[b][i*3 + j] = s;
        }
    g_par[b][9]  = mu[0];   g_par[b][10] = mu[1];   g_par[b][11] = mu[2];
    g_par[b][12] = muGT[0]; g_par[b][13] = muGT[1]; g_par[b][14] = muGT[2];
    g_W[b] = W;
}

// ---------------------------------------------------------------------------
// Fallback K1 (general shapes): 18-moment reduction + solve.
// ---------------------------------------------------------------------------
__global__ void __launch_bounds__(256)
reduce_solve_kernel(const float* __restrict__ pred,
                    const float* __restrict__ gt,
                    const float* __restrict__ w,
                    int N, int blocksPerB)
{
    const int b   = blockIdx.x / blocksPerB;
    const int blk = blockIdx.x % blocksPerB;
    const int t   = threadIdx.x;
    const float* pb = pred + (size_t)b * N * 3;
    const float* gb = gt   + (size_t)b * N * 3;
    const float* wb = w    + (size_t)b * N;

    float acc[NMOM];
#pragma unroll
    for (int i = 0; i < NMOM; i++) acc[i] = 0.f;
    for (int n = blk * blockDim.x + t; n < N; n += blocksPerB * blockDim.x) {
        float wn = wb[n];
        float px = pb[3*n], py = pb[3*n+1], pz = pb[3*n+2];
        float gx = gb[3*n], gy = gb[3*n+1], gz = gb[3*n+2];
        float wpx = wn*px, wpy = wn*py, wpz = wn*pz;
        acc[0] += wn;
        acc[1] += wpx;  acc[2] += wpy;  acc[3] += wpz;
        acc[4] += wn*gx; acc[5] += wn*gy; acc[6] += wn*gz;
        acc[7] += wpx*gx; acc[8] += wpx*gy; acc[9] += wpx*gz;
        acc[10] += wpy*gx; acc[11] += wpy*gy; acc[12] += wpy*gz;
        acc[13] += wpz*gx; acc[14] += wpz*gy; acc[15] += wpz*gz;
        acc[16] += wpx*px + wpy*py + wpz*pz;
        acc[17] += wn*(gx*gx + gy*gy + gz*gz);
    }
    const unsigned mask = 0xffffffffu;
#pragma unroll
    for (int i = 0; i < NMOM; i++)
        for (int o = 16; o > 0; o >>= 1)
            acc[i] += __shfl_down_sync(mask, acc[i], o);
    __shared__ double sred[8][NMOM];
    int warp = t >> 5, lane = t & 31;
    if (lane == 0)
#pragma unroll
        for (int i = 0; i < NMOM; i++) sred[warp][i] = (double)acc[i];
    __syncthreads();
    if (t != 0) return;
    double v[NMOM];
#pragma unroll
    for (int i = 0; i < NMOM; i++) {
        double s = 0.0;
        for (int wi = 0; wi < 8; wi++) s += sred[wi][i];
        g_part[b][blk][i] = s;
    }
    __threadfence();
    unsigned old = atomicInc(&g_cnt[b], (unsigned)(blocksPerB - 1));
    if (old != (unsigned)(blocksPerB - 1)) return;
    __threadfence();
    double vv[NMOM];
    for (int i = 0; i < NMOM; i++) {
        double s = 0.0;
        for (int k = 0; k < blocksPerB; k++) s += g_part[b][k][i];
        vv[i] = s;
    }
    kabsch_solve(vv, b);
    g_num1[b] = 0.0;
    if (b == 0) g_bond = 0.0;
    __threadfence();
}

// ---------------------------------------------------------------------------
// Fused kernel: 256x256 tiles, 512 threads.
// thread t: rows 4*(t&63)+{0..3}, j-eighth (t>>6) -> 32 j's each.
// ---------------------------------------------------------------------------
__global__ void __launch_bounds__(NTHR)
fused_kernel(const float* __restrict__ pred,
             const float* __restrict__ gt,
             const float* __restrict__ w,
             const float* __restrict__ ht,
             float* __restrict__ out,
             int N, int B, int tilesI, int ntri, int precomputed)
{
    const int t  = threadIdx.x;
    const int rp = t & 63;           // row-quad index (64 quads = 256 rows)
    const int jq = t >> 6;           // j eighth 0..7 (32 j's each)
    const int nOff = ntri - tilesI;
    const int blk = blockIdx.x;

    int b, ti, tj;
    bool diag;
    if (blk < B * tilesI) {          // diagonal tiles first
        diag = true;
        b = blk / tilesI;
        ti = tj = blk % tilesI;
    } else {
        diag = false;
        int rem = blk - B * tilesI;
        b = rem / nOff;
        int r2 = rem % nOff;
        ti = 0;
        int rowlen = tilesI - 1;
        while (r2 >= rowlen) { r2 -= rowlen; ti++; rowlen--; }
        tj = ti + 1 + r2;
    }

    const float* pb = pred + (size_t)b * N * 3;
    const float* gb = gt   + (size_t)b * N * 3;
    const float* wb = w    + (size_t)b * N;

    __shared__ float4 sA[TILE];   // (pjx, gjx, pjy, gjy)
    __shared__ float4 sZ[TILE];   // (pjz, gjz, pn2j, gn2j)
    __shared__ float  sW[TILE];
    __shared__ double sred[2][NMOM];
    __shared__ double sredp[NTHR/32];
    __shared__ double sreda[2];

    // ---- load j tile (threads 0..255) ----
    if (t < TILE) {
        int j = tj * TILE + t;
        float px=0.f,py=0.f,pz=0.f,gx=0.f,gy=0.f,gz=0.f,wj=0.f;
        if (j < N) {
            px = pb[3*j]; py = pb[3*j+1]; pz = pb[3*j+2];
            gx = gb[3*j]; gy = gb[3*j+1]; gz = gb[3*j+2];
            wj = wb[j];
        }
        sA[t] = make_float4(px, gx, py, gy);
        sZ[t] = make_float4(pz, gz, px*px+py*py+pz*pz, gx*gx+gy*gy+gz*gz);
        sW[t] = wj;
    }

    // ---- load four i-rows into registers ----
    float pxr[4], pyr[4], pzr[4], gxr[4], gyr[4], gzr[4], wr[4];
#pragma unroll
    for (int r = 0; r < 4; r++) {
        int i = ti * TILE + 4*rp + r;
        pxr[r]=0.f; pyr[r]=0.f; pzr[r]=0.f;
        gxr[r]=0.f; gyr[r]=0.f; gzr[r]=0.f; wr[r]=0.f;
        if (i < N) {
            pxr[r] = pb[3*i]; pyr[r] = pb[3*i+1]; pzr[r] = pb[3*i+2];
            gxr[r] = gb[3*i]; gyr[r] = gb[3*i+1]; gzr[r] = gb[3*i+2];
            wr[r]  = wb[i];
        }
    }

    unsigned long long ax[4], ay[4], az[4], bs[4];
#pragma unroll
    for (int r = 0; r < 4; r++) {
        PACK_F32X2(ax[r], -2.f*pxr[r], -2.f*gxr[r]);
        PACK_F32X2(ay[r], -2.f*pyr[r], -2.f*gyr[r]);
        PACK_F32X2(az[r], -2.f*pzr[r], -2.f*gzr[r]);
        PACK_F32X2(bs[r], pxr[r]*pxr[r]+pyr[r]*pyr[r]+pzr[r]*pzr[r],
                          gxr[r]*gxr[r]+gyr[r]*gyr[r]+gzr[r]*gzr[r]);
    }

    const unsigned mask = 0xffffffffu;
    int warp = t >> 5, lane = t & 31;

    // ---- stats partial (diagonal blocks; threads t<64 own the 256 rows) ----
    if (diag && !precomputed && t < 64) {
        float acc[NMOM];
#pragma unroll
        for (int i = 0; i < NMOM; i++) acc[i] = 0.f;
#pragma unroll
        for (int r = 0; r < 4; r++) {
            float wn = wr[r];
            float px = pxr[r], py = pyr[r], pz = pzr[r];
            float gx = gxr[r], gy = gyr[r], gz = gzr[r];
            float wpx = wn*px, wpy = wn*py, wpz = wn*pz;
            acc[0] += wn;
            acc[1] += wpx;  acc[2] += wpy;  acc[3] += wpz;
            acc[4] += wn*gx; acc[5] += wn*gy; acc[6] += wn*gz;
            acc[7] += wpx*gx; acc[8] += wpx*gy; acc[9] += wpx*gz;
            acc[10] += wpy*gx; acc[11] += wpy*gy; acc[12] += wpy*gz;
            acc[13] += wpz*gx; acc[14] += wpz*gy; acc[15] += wpz*gz;
            acc[16] += wpx*px + wpy*py + wpz*pz;
            acc[17] += wn*(gx*gx + gy*gy + gz*gz);
        }
#pragma unroll
        for (int i = 0; i < NMOM; i++)
            for (int o = 16; o > 0; o >>= 1)
                acc[i] += __shfl_down_sync(mask, acc[i], o);
        if (lane == 0)
#pragma unroll
            for (int i = 0; i < NMOM; i++) sred[warp][i] = (double)acc[i];
    }
    __syncthreads();   // tile fill + sred writes visible

    if (diag && !precomputed && t == 0) {
#pragma unroll
        for (int i = 0; i < NMOM; i++)
            g_part[b][ti][i] = sred[0][i] + sred[1][i];
        __threadfence();
        unsigned old = atomicInc(&g_cnt[b], (unsigned)(tilesI - 1));
        if (old == (unsigned)(tilesI - 1)) {
            __threadfence();
            double vv[NMOM];
            for (int i = 0; i < NMOM; i++) {
                double s = 0.0;
                for (int k = 0; k < tilesI; k++) s += g_part[b][k][i];
                vv[i] = s;
            }
            kabsch_solve(vv, b);
            __threadfence();
            atomicExch(&g_ready[b], 1);
        }
    }

    // ---- cross-term loop: acc_r += wj * sqrt(dp2*dg2), 4 rows x 32 j ----
    float accr[4] = {0.f, 0.f, 0.f, 0.f};
    const int kbase = jq * 32;
#pragma unroll 4
    for (int kk = 0; kk < 32; kk++) {
        int k = kbase + kk;
        ulonglong2 A = *reinterpret_cast<const ulonglong2*>(&sA[k]);
        ulonglong2 Z = *reinterpret_cast<const ulonglong2*>(&sZ[k]);
        float wj = sW[k];
#pragma unroll
        for (int r = 0; r < 4; r++) {
            unsigned long long c;
            FMA_F32X2(c, az[r], Z.x, Z.y);   // -2z*zj + (pn2j,gn2j)
            FMA_F32X2(c, ay[r], A.y, c);
            FMA_F32X2(c, ax[r], A.x, c);
            ADD_F32X2(c, c, bs[r]);          // -> (dp2, dg2)
            float dp2, dg2;
            UNPACK_F32X2(dp2, dg2, c);
            float prod = fmaxf(dp2 * dg2, 0.f);
            float s = fsqrt_approx(prod);    // = dp*dg
            accr[r] = fmaf(wj, s, accr[r]);
        }
    }

    double tot = (double)(accr[0]*wr[0]) + (double)(accr[1]*wr[1])
               + (double)(accr[2]*wr[2]) + (double)(accr[3]*wr[3]);
    if (!diag) tot *= 2.0;           // symmetry
    for (int o = 16; o > 0; o >>= 1)
        tot += __shfl_down_sync(mask, tot, o);
    if (lane == 0) sredp[warp] = tot;

    // ---- fused alignment loss (diagonal blocks; threads t<64) ----
    if (diag) {
        if (!precomputed && t == 0) {
            int r;
            do {
                asm volatile("ld.acquire.gpu.b32 %0, [%1];"
                             : "=r"(r) : "l"(&g_ready[b]) : "memory");
            } while (r == 0);
        }
        __syncthreads();
        if (t < 64) {
            float R00 = g_par[b][0], R01 = g_par[b][1], R02 = g_par[b][2];
            float R10 = g_par[b][3], R11 = g_par[b][4], R12 = g_par[b][5];
            float R20 = g_par[b][6], R21 = g_par[b][7], R22 = g_par[b][8];
            float mux = g_par[b][9],  muy = g_par[b][10], muz = g_par[b][11];
            float mgx = g_par[b][12], mgy = g_par[b][13], mgz = g_par[b][14];

            float alf = 0.f;
#pragma unroll
            for (int r = 0; r < 4; r++) {
                float gx = gxr[r] - mux, gy = gyr[r] - muy, gz = gzr[r] - muz;
                float axv = R00*gx + R01*gy + R02*gz + mgx;
                float ayv = R10*gx + R11*gy + R12*gz + mgy;
                float azv = R20*gx + R21*gy + R22*gz + mgz;
                float dx = pxr[r] - axv, dy = pyr[r] - ayv, dz = pzr[r] - azv;
                alf += wr[r] * fsqrt_approx(dx*dx + dy*dy + dz*dz);
            }
            double al = (double)alf;
            for (int o = 16; o > 0; o >>= 1)
                al += __shfl_down_sync(mask, al, o);
            if (lane == 0) sreda[warp] = al;
        }
        __syncthreads();
        if (t == 0)
            atomicAdd(&g_num1[b], sreda[0] + sreda[1]);
    }
    __syncthreads();

    // ---- block totals + global completion ----
    if (t == 0) {
        double s = 0.0;
        for (int wi = 0; wi < NTHR/32; wi++) s += sredp[wi];
        atomicAdd(&g_bond, s);
        __threadfence();
        unsigned old = atomicInc(&g_done, (unsigned)(gridDim.x - 1));
        if (old == (unsigned)(gridDim.x - 1)) {
            __threadfence();
            double sw = 0.0, sw2 = 0.0, sn = 0.0, scl = 0.0;
            for (int bb = 0; bb < B; bb++) {
                double W = g_W[bb];
                sw += W; sw2 += W * W; sn += g_num1[bb]; scl += g_closed[bb];
            }
            // bond numerator = closed - 2 * sum wiwj dp*dg
            double loss = sn / sw + (scl - 2.0 * g_bond) / sw2;
            for (int bb = 0; bb < B; bb++) {
                double h = (double)ht[bb];
                out[bb] = (float)(((h*h + 256.0) / ((h + 16.0) * (h + 16.0))) * loss);
            }
            g_bond = 0.0;
            for (int bb = 0; bb < B; bb++) { g_num1[bb] = 0.0; g_ready[bb] = 0; }
            __threadfence();
        }
    }
}

extern "C" void kernel_launch(void* const* d_in, const int* in_sizes, int n_in,
                              void* d_out, int out_size)
{
    const float* pred = (const float*)d_in[0];
    const float* gt   = (const float*)d_in[1];
    const float* ht   = (const float*)d_in[2];
    const float* w    = (const float*)d_in[3];
    int B = in_sizes[2];
    int N = in_sizes[3] / B;

    int tilesI = (N + TILE - 1) / TILE;
    int ntri = tilesI * (tilesI + 1) / 2;
    int grid = B * ntri;

    if (grid <= 148 && tilesI <= MAXBLK && B <= MAXB) {
        fused_kernel<<<grid, NTHR>>>(pred, gt, w, ht, (float*)d_out,
                                     N, B, tilesI, ntri, 0);
    } else {
        int blocksPerB = (N + 255) / 256;
        if (blocksPerB > MAXBLK) blocksPerB = MAXBLK;
        reduce_solve_kernel<<<B * blocksPerB, 256>>>(pred, gt, w, N, blocksPerB);
        fused_kernel<<<grid, NTHR>>>(pred, gt, w, ht, (float*)d_out,
                                     N, B, tilesI, ntri, 1);
    }
}